// round 1
// baseline (speedup 1.0000x reference)
#include <cuda_runtime.h>

// CIN (xDeepFM) fused 2-layer kernel for GB300 sm_103a.
// B=4096, F=32, D=32, layers [128,128].
// out[b, n]      = sum_d relu( sum_{h,m} x[b,h,d] x[b,m,d]      W0[h*32+m,  n] )   n in [0,128)
// out[b, 128+n]  = sum_d relu( sum_{h,m} x[b,h,d] cur0[b,m,d]   W1[h*128+m, n] )
//
// One CTA per batch. 256 threads = (n in [0,128)) x (d-half in {0,1}).
// Each thread holds 16 d-accumulators as 8 packed f32x2 regs; math uses
// fma.rn.f32x2 (Blackwell packed fp32 FFMA2, 2 MACs/lane).

namespace {
constexpr int F_   = 32;
constexpr int D_   = 32;
constexpr int N1_  = 128;   // layer0 outputs (= layer1 "m" extent)
constexpr int K0_  = F_ * F_;    // 1024
constexpr int K1_  = F_ * N1_;   // 4096
constexpr int KC_  = 32;         // K-chunk
constexpr int NT_  = 256;        // threads per CTA
}

__device__ __forceinline__ unsigned long long ffma2(unsigned long long a,
                                                    unsigned long long b,
                                                    unsigned long long c) {
    unsigned long long d;
    asm("fma.rn.f32x2 %0, %1, %2, %3;" : "=l"(d) : "l"(a), "l"(b), "l"(c));
    return d;
}

__device__ __forceinline__ unsigned long long pack2(float x) {
    unsigned long long r;
    asm("mov.b64 %0, {%1, %1};" : "=l"(r) : "f"(x));
    return r;
}

__global__ __launch_bounds__(NT_) void cin_fused_kernel(
    const float* __restrict__ x,    // [B, 32, 32]
    const float* __restrict__ w0,   // [1024, 128]
    const float* __restrict__ w1,   // [4096, 128]
    float* __restrict__ out)        // [B, 256]
{
    __shared__ __align__(16) float U[F_ * D_];        // U[h*32 + d]
    __shared__ __align__(16) float C0[D_][N1_ + 1];   // relu(layer0), stride 129 (conflict-free)
    __shared__ __align__(16) float Zc[KC_][D_];       // Z chunk [k_local][d]
    __shared__ __align__(16) float Wc[KC_ * N1_];     // W chunk [k_local][n]

    const int b  = blockIdx.x;
    const int t  = threadIdx.x;
    const int n  = t & (N1_ - 1);   // output column, 0..127
    const int dh = t >> 7;          // d half: 0 -> d 0..15, 1 -> d 16..31

    // Load this batch's inputs: 1024 floats = 256 float4, fully coalesced.
    reinterpret_cast<float4*>(U)[t] =
        reinterpret_cast<const float4*>(x + (size_t)b * (F_ * D_))[t];
    __syncthreads();

    unsigned long long acc[8];

    // ---------------- Layer 0: K = 1024, Z[k=h*32+m][d] = U[h][d]*U[m][d] ----
    #pragma unroll
    for (int j = 0; j < 8; ++j) acc[j] = 0ull;

    for (int kb = 0; kb < K0_; kb += KC_) {
        // Stage Z chunk: 32x32 values, 4 per thread.
        for (int idx = t; idx < KC_ * D_; idx += NT_) {
            const int kl = idx >> 5, d = idx & 31;
            const int k = kb + kl;
            Zc[kl][d] = U[((k >> 5) << 5) + d] * U[((k & 31) << 5) + d];
        }
        // Stage W chunk: 32 rows x 128 floats = 1024 float4, 4 per thread.
        {
            const float4* src = reinterpret_cast<const float4*>(w0 + (size_t)kb * N1_);
            float4* dst = reinterpret_cast<float4*>(Wc);
            #pragma unroll
            for (int r = 0; r < (KC_ * N1_ / 4) / NT_; ++r)
                dst[r * NT_ + t] = src[r * NT_ + t];
        }
        __syncthreads();

        #pragma unroll 8
        for (int kl = 0; kl < KC_; ++kl) {
            const unsigned long long w2 = pack2(Wc[kl * N1_ + n]);
            const unsigned long long* z2 =
                reinterpret_cast<const unsigned long long*>(&Zc[kl][dh * 16]);
            #pragma unroll
            for (int j = 0; j < 8; ++j) acc[j] = ffma2(z2[j], w2, acc[j]);
        }
        __syncthreads();
    }

    // Epilogue 0: relu -> C0 smem (for layer 1) + partial d-sum for output.
    float sum0 = 0.f;
    #pragma unroll
    for (int j = 0; j < 8; ++j) {
        float lo = __uint_as_float((unsigned int)(acc[j] & 0xffffffffull));
        float hi = __uint_as_float((unsigned int)(acc[j] >> 32));
        lo = fmaxf(lo, 0.f);
        hi = fmaxf(hi, 0.f);
        const int d = dh * 16 + 2 * j;
        C0[d][n]     = lo;
        C0[d + 1][n] = hi;
        sum0 += lo + hi;
    }
    __syncthreads();                       // C0 complete before any reuse

    float* red = &Zc[0][0];                // reuse Zc as 128-float reduce buffer
    if (dh == 1) red[n] = sum0;
    __syncthreads();
    if (dh == 0) out[(size_t)b * 256 + n] = sum0 + red[n];
    __syncthreads();                       // protect red before Zc restaging

    // ---------------- Layer 1: K = 4096, Z[k=h*128+m][d] = U[h][d]*C0[d][m] --
    #pragma unroll
    for (int j = 0; j < 8; ++j) acc[j] = 0ull;

    for (int kb = 0; kb < K1_; kb += KC_) {
        for (int idx = t; idx < KC_ * D_; idx += NT_) {
            const int kl = idx >> 5, d = idx & 31;
            const int k = kb + kl;
            Zc[kl][d] = U[((k >> 7) << 5) + d] * C0[d][k & (N1_ - 1)];
        }
        {
            const float4* src = reinterpret_cast<const float4*>(w1 + (size_t)kb * N1_);
            float4* dst = reinterpret_cast<float4*>(Wc);
            #pragma unroll
            for (int r = 0; r < (KC_ * N1_ / 4) / NT_; ++r)
                dst[r * NT_ + t] = src[r * NT_ + t];
        }
        __syncthreads();

        #pragma unroll 8
        for (int kl = 0; kl < KC_; ++kl) {
            const unsigned long long w2 = pack2(Wc[kl * N1_ + n]);
            const unsigned long long* z2 =
                reinterpret_cast<const unsigned long long*>(&Zc[kl][dh * 16]);
            #pragma unroll
            for (int j = 0; j < 8; ++j) acc[j] = ffma2(z2[j], w2, acc[j]);
        }
        __syncthreads();
    }

    // Epilogue 1: relu + d-sum in registers (cur1 never materialized).
    float sum1 = 0.f;
    #pragma unroll
    for (int j = 0; j < 8; ++j) {
        const float lo = __uint_as_float((unsigned int)(acc[j] & 0xffffffffull));
        const float hi = __uint_as_float((unsigned int)(acc[j] >> 32));
        sum1 += fmaxf(lo, 0.f) + fmaxf(hi, 0.f);
    }
    if (dh == 1) red[n] = sum1;
    __syncthreads();
    if (dh == 0) out[(size_t)b * 256 + 128 + n] = sum1 + red[n];
}

extern "C" void kernel_launch(void* const* d_in, const int* in_sizes, int n_in,
                              void* d_out, int out_size) {
    const float* x  = (const float*)d_in[0];   // inputs   [4096,32,32]
    const float* w0 = (const float*)d_in[1];   // filter_0 [1,1024,128]
    const float* w1 = (const float*)d_in[2];   // filter_1 [1,4096,128]
    float* out = (float*)d_out;                // [4096, 256]
    (void)in_sizes; (void)n_in; (void)out_size;

    cin_fused_kernel<<<4096, NT_>>>(x, w0, w1, out);
}

// round 2
// speedup vs baseline: 2.8270x; 2.8270x over previous
#include <cuda_runtime.h>

// CIN (xDeepFM) fused 2-layer kernel, round 2 — register-blocked 4n x 16d.
// B=4096, F=32, D=32, layers [128,128].
// out[b, n]      = sum_d relu( sum_{h,m} x[b,h,d] x[b,m,d]    W0[h*32+m,  n] )
// out[b, 128+n]  = sum_d relu( sum_{h,m} x[b,h,d] c0[b,m,d]   W1[h*128+m, n] )
//
// One CTA (64 threads) per batch. Thread (q, dh) owns n in [4q,4q+4) x 16 d's.
// 32 packed f32x2 accumulators per thread; inner k-step: 4 broadcast LDS.128
// (z) + 1 conflict-free LDS.128 (w) feed 32 fma.rn.f32x2.

namespace {
constexpr int F_  = 32;
constexpr int D_  = 32;
constexpr int N1_ = 128;
constexpr int K0_ = F_ * F_;    // 1024
constexpr int K1_ = F_ * N1_;   // 4096
constexpr int KC_ = 32;         // K-chunk
constexpr int NT_ = 64;
constexpr int US_ = 33;         // U row stride (conflict-free staging reads)
constexpr int ZS_ = 36;         // Zc row stride (16B-aligned, low-conflict)
constexpr int CS_ = 129;        // C0 row stride
}

typedef unsigned long long ull;

__device__ __forceinline__ ull ffma2(ull a, ull b, ull c) {
    ull d;
    asm("fma.rn.f32x2 %0, %1, %2, %3;" : "=l"(d) : "l"(a), "l"(b), "l"(c));
    return d;
}
__device__ __forceinline__ ull pack2(float x) {
    ull r;
    asm("mov.b64 %0, {%1, %1};" : "=l"(r) : "f"(x));
    return r;
}
__device__ __forceinline__ ull packf(float lo, float hi) {
    ull r;
    asm("mov.b64 %0, {%1, %2};" : "=l"(r) : "f"(lo), "f"(hi));
    return r;
}
__device__ __forceinline__ void unpack2(ull v, float& lo, float& hi) {
    asm("mov.b64 {%0, %1}, %2;" : "=f"(lo), "=f"(hi) : "l"(v));
}

__global__ __launch_bounds__(NT_) void cin_fused_kernel(
    const float* __restrict__ x,    // [B, 32, 32]
    const float* __restrict__ w0,   // [1024, 128]
    const float* __restrict__ w1,   // [4096, 128]
    float* __restrict__ out)        // [B, 256]
{
    __shared__ __align__(16) float U[F_ * US_];       // U[h*33 + d]
    __shared__ __align__(16) float C0[D_ * CS_];      // C0[d*129 + n]
    __shared__ __align__(16) float Zc[KC_ * ZS_];     // Zc[kl*36 + d]
    __shared__ __align__(16) float4 Wc4[KC_ * 32];    // Wc[kl][n] as float4

    const int b  = blockIdx.x;
    const int t  = threadIdx.x;
    const int q  = t & 31;          // n-quad: n0 = 4q
    const int dh = t >> 5;          // d-half: d0 = 16*dh
    const int d0 = dh << 4;
    const int n0 = q << 2;

    // Staging split: thread handles Zc row skl, d range [sd0, sd0+16)
    const int skl = t >> 1;
    const int sd0 = (t & 1) << 4;

    // ---- load inputs into padded smem (coalesced global reads) ----
    for (int i = t; i < F_ * D_; i += NT_)
        U[(i >> 5) * US_ + (i & 31)] = x[(size_t)b * (F_ * D_) + i];

    ull acc[32];

    // ================= Layer 0: K=1024, Z[k=h*32+m][d]=U[h][d]*U[m][d] ======
    #pragma unroll
    for (int j = 0; j < 32; ++j) acc[j] = 0ull;

    for (int kb = 0; kb < K0_; kb += KC_) {
        __syncthreads();
        // stage Z: h constant within chunk, m = kl
        {
            const int h = kb >> 5;
            const float* uh = &U[h * US_ + sd0];
            const float* um = &U[skl * US_ + sd0];
            float* zd = &Zc[skl * ZS_ + sd0];
            #pragma unroll
            for (int c = 0; c < 16; ++c) zd[c] = uh[c] * um[c];
        }
        // stage W chunk: 1024 float4, 16 per thread, coalesced
        {
            const float4* src = reinterpret_cast<const float4*>(w0 + (size_t)kb * N1_);
            #pragma unroll
            for (int r = 0; r < 16; ++r) Wc4[r * NT_ + t] = src[r * NT_ + t];
        }
        __syncthreads();

        #pragma unroll 4
        for (int kl = 0; kl < KC_; ++kl) {
            const float* zrow = &Zc[kl * ZS_ + d0];
            const float4 za = *reinterpret_cast<const float4*>(zrow);
            const float4 zb = *reinterpret_cast<const float4*>(zrow + 4);
            const float4 zc = *reinterpret_cast<const float4*>(zrow + 8);
            const float4 zd = *reinterpret_cast<const float4*>(zrow + 12);
            ull z[8];
            z[0] = packf(za.x, za.y); z[1] = packf(za.z, za.w);
            z[2] = packf(zb.x, zb.y); z[3] = packf(zb.z, zb.w);
            z[4] = packf(zc.x, zc.y); z[5] = packf(zc.z, zc.w);
            z[6] = packf(zd.x, zd.y); z[7] = packf(zd.z, zd.w);
            const float4 wv = Wc4[kl * 32 + q];
            const ull w0p = pack2(wv.x), w1p = pack2(wv.y);
            const ull w2p = pack2(wv.z), w3p = pack2(wv.w);
            #pragma unroll
            for (int p = 0; p < 8; ++p) {
                acc[p]      = ffma2(z[p], w0p, acc[p]);
                acc[8 + p]  = ffma2(z[p], w1p, acc[8 + p]);
                acc[16 + p] = ffma2(z[p], w2p, acc[16 + p]);
                acc[24 + p] = ffma2(z[p], w3p, acc[24 + p]);
            }
        }
    }
    __syncthreads();

    // ---- epilogue 0: relu -> C0, partial d-sums -> out[b, 0..128) ----
    {
        float sums[4] = {0.f, 0.f, 0.f, 0.f};
        #pragma unroll
        for (int nn = 0; nn < 4; ++nn) {
            #pragma unroll
            for (int p = 0; p < 8; ++p) {
                float lo, hi;
                unpack2(acc[nn * 8 + p], lo, hi);
                lo = fmaxf(lo, 0.f); hi = fmaxf(hi, 0.f);
                const int d = d0 + 2 * p;
                C0[d * CS_ + n0 + nn]       = lo;
                C0[(d + 1) * CS_ + n0 + nn] = hi;
                sums[nn] += lo + hi;
            }
        }
        float* red = Zc;  // 128-float scratch (Zc free between chunks)
        if (dh == 1) {
            #pragma unroll
            for (int nn = 0; nn < 4; ++nn) red[n0 + nn] = sums[nn];
        }
        __syncthreads();
        if (dh == 0) {
            float4 o;
            o.x = sums[0] + red[n0];
            o.y = sums[1] + red[n0 + 1];
            o.z = sums[2] + red[n0 + 2];
            o.w = sums[3] + red[n0 + 3];
            reinterpret_cast<float4*>(out + (size_t)b * 256)[q] = o;
        }
    }

    // ================= Layer 1: K=4096, Z[k=h*128+m][d]=U[h][d]*C0[d][m] ====
    #pragma unroll
    for (int j = 0; j < 32; ++j) acc[j] = 0ull;

    for (int kb = 0; kb < K1_; kb += KC_) {
        __syncthreads();
        {
            const int h = kb >> 7;               // constant within chunk
            const int m = (kb & (N1_ - 1)) + skl; // no wrap within chunk
            const float* uh = &U[h * US_ + sd0];
            float* zd = &Zc[skl * ZS_ + sd0];
            #pragma unroll
            for (int c = 0; c < 16; ++c)
                zd[c] = uh[c] * C0[(sd0 + c) * CS_ + m];
        }
        {
            const float4* src = reinterpret_cast<const float4*>(w1 + (size_t)kb * N1_);
            #pragma unroll
            for (int r = 0; r < 16; ++r) Wc4[r * NT_ + t] = src[r * NT_ + t];
        }
        __syncthreads();

        #pragma unroll 4
        for (int kl = 0; kl < KC_; ++kl) {
            const float* zrow = &Zc[kl * ZS_ + d0];
            const float4 za = *reinterpret_cast<const float4*>(zrow);
            const float4 zb = *reinterpret_cast<const float4*>(zrow + 4);
            const float4 zc = *reinterpret_cast<const float4*>(zrow + 8);
            const float4 zd = *reinterpret_cast<const float4*>(zrow + 12);
            ull z[8];
            z[0] = packf(za.x, za.y); z[1] = packf(za.z, za.w);
            z[2] = packf(zb.x, zb.y); z[3] = packf(zb.z, zb.w);
            z[4] = packf(zc.x, zc.y); z[5] = packf(zc.z, zc.w);
            z[6] = packf(zd.x, zd.y); z[7] = packf(zd.z, zd.w);
            const float4 wv = Wc4[kl * 32 + q];
            const ull w0p = pack2(wv.x), w1p = pack2(wv.y);
            const ull w2p = pack2(wv.z), w3p = pack2(wv.w);
            #pragma unroll
            for (int p = 0; p < 8; ++p) {
                acc[p]      = ffma2(z[p], w0p, acc[p]);
                acc[8 + p]  = ffma2(z[p], w1p, acc[8 + p]);
                acc[16 + p] = ffma2(z[p], w2p, acc[16 + p]);
                acc[24 + p] = ffma2(z[p], w3p, acc[24 + p]);
            }
        }
    }
    __syncthreads();

    // ---- epilogue 1: relu + d-sum (cur1 never materialized) ----
    {
        float sums[4] = {0.f, 0.f, 0.f, 0.f};
        #pragma unroll
        for (int nn = 0; nn < 4; ++nn) {
            #pragma unroll
            for (int p = 0; p < 8; ++p) {
                float lo, hi;
                unpack2(acc[nn * 8 + p], lo, hi);
                sums[nn] += fmaxf(lo, 0.f) + fmaxf(hi, 0.f);
            }
        }
        float* red = Zc;
        if (dh == 1) {
            #pragma unroll
            for (int nn = 0; nn < 4; ++nn) red[n0 + nn] = sums[nn];
        }
        __syncthreads();
        if (dh == 0) {
            float4 o;
            o.x = sums[0] + red[n0];
            o.y = sums[1] + red[n0 + 1];
            o.z = sums[2] + red[n0 + 2];
            o.w = sums[3] + red[n0 + 3];
            reinterpret_cast<float4*>(out + (size_t)b * 256 + 128)[q] = o;
        }
    }
}

extern "C" void kernel_launch(void* const* d_in, const int* in_sizes, int n_in,
                              void* d_out, int out_size) {
    const float* x  = (const float*)d_in[0];   // inputs   [4096,32,32]
    const float* w0 = (const float*)d_in[1];   // filter_0 [1,1024,128]
    const float* w1 = (const float*)d_in[2];   // filter_1 [1,4096,128]
    float* out = (float*)d_out;                // [4096, 256]
    (void)in_sizes; (void)n_in; (void)out_size;

    cin_fused_kernel<<<4096, NT_>>>(x, w0, w1, out);
}

// round 3
// speedup vs baseline: 3.0785x; 1.0890x over previous
#include <cuda_runtime.h>

// CIN (xDeepFM) fused 2-layer kernel, round 3.
// B=4096, F=32, D=32, layers [128,128].
// One CTA = 2 batches, 128 threads. Thread (bs, q, dh) owns batch bs,
// n in [4q,4q+4) x 16 d's. 32 packed f32x2 accumulators per thread.
// W chunks are register-prefetched (double-buffered) and shared by both
// batches; Z chunks staged per batch in smem.

namespace {
constexpr int F_  = 32;
constexpr int D_  = 32;
constexpr int N1_ = 128;
constexpr int K0_ = F_ * F_;    // 1024
constexpr int K1_ = F_ * N1_;   // 4096
constexpr int KC_ = 32;         // K-chunk
constexpr int NT_ = 128;        // threads per CTA (2 batches x 64)
constexpr int US_ = 33;         // U row stride
constexpr int ZS_ = 36;         // Zc row stride
constexpr int CS_ = 129;        // C0 row stride
constexpr int WR_ = 8;          // float4 per thread per W chunk = KC_*N1_/4/NT_
}

typedef unsigned long long ull;

__device__ __forceinline__ ull ffma2(ull a, ull b, ull c) {
    ull d;
    asm("fma.rn.f32x2 %0, %1, %2, %3;" : "=l"(d) : "l"(a), "l"(b), "l"(c));
    return d;
}
__device__ __forceinline__ ull pack2(float x) {
    ull r;
    asm("mov.b64 %0, {%1, %1};" : "=l"(r) : "f"(x));
    return r;
}
__device__ __forceinline__ ull packf(float lo, float hi) {
    ull r;
    asm("mov.b64 %0, {%1, %2};" : "=l"(r) : "f"(lo), "f"(hi));
    return r;
}
__device__ __forceinline__ void unpack2(ull v, float& lo, float& hi) {
    asm("mov.b64 {%0, %1}, %2;" : "=f"(lo), "=f"(hi) : "l"(v));
}

// One K-chunk of the GEMM: 32 k-steps, 4n x 16d per thread.
__device__ __forceinline__ void compute_chunk(ull* acc, const float* zbase,
                                              const float4* wc4,
                                              int d0, int q) {
    #pragma unroll 4
    for (int kl = 0; kl < KC_; ++kl) {
        const float* zrow = zbase + kl * ZS_ + d0;
        const float4 za = *reinterpret_cast<const float4*>(zrow);
        const float4 zb = *reinterpret_cast<const float4*>(zrow + 4);
        const float4 zc = *reinterpret_cast<const float4*>(zrow + 8);
        const float4 zd = *reinterpret_cast<const float4*>(zrow + 12);
        ull z[8];
        z[0] = packf(za.x, za.y); z[1] = packf(za.z, za.w);
        z[2] = packf(zb.x, zb.y); z[3] = packf(zb.z, zb.w);
        z[4] = packf(zc.x, zc.y); z[5] = packf(zc.z, zc.w);
        z[6] = packf(zd.x, zd.y); z[7] = packf(zd.z, zd.w);
        const float4 wv = wc4[kl * 32 + q];
        const ull w0p = pack2(wv.x), w1p = pack2(wv.y);
        const ull w2p = pack2(wv.z), w3p = pack2(wv.w);
        #pragma unroll
        for (int p = 0; p < 8; ++p) {
            acc[p]      = ffma2(z[p], w0p, acc[p]);
            acc[8 + p]  = ffma2(z[p], w1p, acc[8 + p]);
            acc[16 + p] = ffma2(z[p], w2p, acc[16 + p]);
            acc[24 + p] = ffma2(z[p], w3p, acc[24 + p]);
        }
    }
}

__global__ __launch_bounds__(NT_) void cin_fused_kernel(
    const float* __restrict__ x,    // [B, 32, 32]
    const float* __restrict__ w0,   // [1024, 128]
    const float* __restrict__ w1,   // [4096, 128]
    float* __restrict__ out)        // [B, 256]
{
    __shared__ __align__(16) float U[2][F_ * US_];
    __shared__ __align__(16) float C0[2][D_ * CS_];
    __shared__ __align__(16) float Zc[2][KC_ * ZS_];
    __shared__ __align__(16) float4 Wc4[KC_ * 32];   // shared by both batches

    const int t   = threadIdx.x;
    const int bs  = t >> 6;          // batch within CTA
    const int t6  = t & 63;
    const int q   = t6 & 31;         // n-quad
    const int dh  = t6 >> 5;         // d-half
    const int d0  = dh << 4;
    const int n0  = q << 2;
    const int skl = t6 >> 1;         // staging: Z row
    const int sd0 = (t6 & 1) << 4;   // staging: d offset
    const size_t b = (size_t)blockIdx.x * 2 + bs;

    // Load both batches' inputs into padded smem (coalesced).
    for (int i = t; i < 2 * F_ * D_; i += NT_) {
        const int lb = i >> 10, r = i & 1023;
        U[lb][(r >> 5) * US_ + (r & 31)] =
            x[((size_t)blockIdx.x * 2 + lb) * (F_ * D_) + r];
    }

    ull acc[32];
    float4 wreg[WR_];

    // ================= Layer 0: K=1024 ======================================
    #pragma unroll
    for (int j = 0; j < 32; ++j) acc[j] = 0ull;

    {   // prefetch chunk 0
        const float4* src = reinterpret_cast<const float4*>(w0);
        #pragma unroll
        for (int r = 0; r < WR_; ++r) wreg[r] = src[r * NT_ + t];
    }

    for (int kb = 0; kb < K0_; kb += KC_) {
        __syncthreads();   // prev compute done reading Wc4/Zc (iter0: U loads)
        #pragma unroll
        for (int r = 0; r < WR_; ++r) Wc4[r * NT_ + t] = wreg[r];
        {   // stage Z for my batch: h constant within chunk, m = skl
            const int h = kb >> 5;
            const float* uh = &U[bs][h * US_ + sd0];
            const float* um = &U[bs][skl * US_ + sd0];
            float* zd = &Zc[bs][skl * ZS_ + sd0];
            #pragma unroll
            for (int c = 0; c < 16; ++c) zd[c] = uh[c] * um[c];
        }
        __syncthreads();
        if (kb + KC_ < K0_) {   // prefetch next chunk (hidden by compute)
            const float4* src =
                reinterpret_cast<const float4*>(w0 + (size_t)(kb + KC_) * N1_);
            #pragma unroll
            for (int r = 0; r < WR_; ++r) wreg[r] = src[r * NT_ + t];
        } else {                // prefetch layer-1 chunk 0
            const float4* src = reinterpret_cast<const float4*>(w1);
            #pragma unroll
            for (int r = 0; r < WR_; ++r) wreg[r] = src[r * NT_ + t];
        }
        compute_chunk(acc, &Zc[bs][0], Wc4, d0, q);
    }
    __syncthreads();   // all layer-0 compute done

    // ---- epilogue 0: relu -> C0, partial d-sums -> out[b, 0..128) ----
    {
        float sums[4] = {0.f, 0.f, 0.f, 0.f};
        #pragma unroll
        for (int nn = 0; nn < 4; ++nn) {
            #pragma unroll
            for (int p = 0; p < 8; ++p) {
                float lo, hi;
                unpack2(acc[nn * 8 + p], lo, hi);
                lo = fmaxf(lo, 0.f); hi = fmaxf(hi, 0.f);
                const int d = d0 + 2 * p;
                C0[bs][d * CS_ + n0 + nn]       = lo;
                C0[bs][(d + 1) * CS_ + n0 + nn] = hi;
                sums[nn] += lo + hi;
            }
        }
        float* red = &Zc[bs][0];   // per-batch 128-float scratch
        if (dh == 1) {
            #pragma unroll
            for (int nn = 0; nn < 4; ++nn) red[n0 + nn] = sums[nn];
        }
        __syncthreads();
        if (dh == 0) {
            float4 o;
            o.x = sums[0] + red[n0];
            o.y = sums[1] + red[n0 + 1];
            o.z = sums[2] + red[n0 + 2];
            o.w = sums[3] + red[n0 + 3];
            reinterpret_cast<float4*>(out + b * 256)[q] = o;
        }
    }

    // ================= Layer 1: K=4096 ======================================
    #pragma unroll
    for (int j = 0; j < 32; ++j) acc[j] = 0ull;

    for (int kb = 0; kb < K1_; kb += KC_) {
        __syncthreads();   // prev compute done; epilogue red reads done
        #pragma unroll
        for (int r = 0; r < WR_; ++r) Wc4[r * NT_ + t] = wreg[r];
        {   // stage Z: h constant within chunk, m = (kb&127)+skl
            const int h = kb >> 7;
            const int m = (kb & (N1_ - 1)) + skl;
            const float* uh = &U[bs][h * US_ + sd0];
            float* zd = &Zc[bs][skl * ZS_ + sd0];
            #pragma unroll
            for (int c = 0; c < 16; ++c)
                zd[c] = uh[c] * C0[bs][(sd0 + c) * CS_ + m];
        }
        __syncthreads();
        if (kb + KC_ < K1_) {
            const float4* src =
                reinterpret_cast<const float4*>(w1 + (size_t)(kb + KC_) * N1_);
            #pragma unroll
            for (int r = 0; r < WR_; ++r) wreg[r] = src[r * NT_ + t];
        }
        compute_chunk(acc, &Zc[bs][0], Wc4, d0, q);
    }
    __syncthreads();

    // ---- epilogue 1: relu + d-sum (cur1 never materialized) ----
    {
        float sums[4] = {0.f, 0.f, 0.f, 0.f};
        #pragma unroll
        for (int nn = 0; nn < 4; ++nn) {
            #pragma unroll
            for (int p = 0; p < 8; ++p) {
                float lo, hi;
                unpack2(acc[nn * 8 + p], lo, hi);
                sums[nn] += fmaxf(lo, 0.f) + fmaxf(hi, 0.f);
            }
        }
        float* red = &Zc[bs][0];
        if (dh == 1) {
            #pragma unroll
            for (int nn = 0; nn < 4; ++nn) red[n0 + nn] = sums[nn];
        }
        __syncthreads();
        if (dh == 0) {
            float4 o;
            o.x = sums[0] + red[n0];
            o.y = sums[1] + red[n0 + 1];
            o.z = sums[2] + red[n0 + 2];
            o.w = sums[3] + red[n0 + 3];
            reinterpret_cast<float4*>(out + b * 256 + 128)[q] = o;
        }
    }
}

extern "C" void kernel_launch(void* const* d_in, const int* in_sizes, int n_in,
                              void* d_out, int out_size) {
    const float* x  = (const float*)d_in[0];   // inputs   [4096,32,32]
    const float* w0 = (const float*)d_in[1];   // filter_0 [1,1024,128]
    const float* w1 = (const float*)d_in[2];   // filter_1 [1,4096,128]
    float* out = (float*)d_out;                // [4096, 256]
    (void)in_sizes; (void)n_in; (void)out_size;

    cin_fused_kernel<<<4096 / 2, NT_>>>(x, w0, w1, out);
}

// round 6
// speedup vs baseline: 4.0116x; 1.3031x over previous
#include <cuda_runtime.h>

// CIN (xDeepFM) fused 2-layer kernel, round 5 — mma.sync tf32 (non-'a' PTX).
// B=4096, F=32, D=32, layers [128,128].
//
// GEMM view per batch: D32 sample-rows x 128 n, K0=1024, K1=4096.
//   z0[d][k=h*32+m]  = u[h][d]*u[m][d]
//   z1[d][k=h*128+m] = u[h][d]*relu(cur0)[m][d]
// Precision: z split (zh=cvt.rna.tf32, zl=z-zh); W converted rna.tf32 once.
//   acc += zh*W + zl*W   (2 mma terms, fp32 accumulate)
//
// CTA = 4 batches = M128 x N128, 256 threads, 8 warps of M64 x N32.
// A fragments built in registers (no A smem); W chunks (KC=32) reg-prefetched
// into double-buffered smem; one __syncthreads per chunk.

typedef unsigned int u32;

namespace {
constexpr int NT    = 256;
constexpr int L0CH  = 32;     // layer-0 chunks (K=1024/32)
constexpr int NCH   = 160;    // + layer-1 chunks (K=4096/32)
constexpr int USTR  = 36;     // Ud  [d][h] stride (bank = 4D+L, injective)
constexpr int CSTR  = 132;    // C0  [d][m] stride (bank = 4D+L, injective)
constexpr int WSTR  = 136;    // Wt  [k][n] stride (bank = 8L+D, injective)
constexpr int UD_SZ = 32 * USTR;   // 1152 floats / batch
constexpr int C0_SZ = 32 * CSTR;   // 4224 floats / batch
constexpr int WT_SZ = 32 * WSTR;   // 4352 floats / buffer
constexpr int UD_OFF = 0;
constexpr int C0_OFF = UD_OFF + 4 * UD_SZ;   // 4608
constexpr int WT_OFF = C0_OFF + 4 * C0_SZ;   // 21504
constexpr int SMEM_F = WT_OFF + 2 * WT_SZ;   // 30208 floats = 118 KB
}

__device__ __forceinline__ u32 cvt_tf32(float x) {
    u32 h;
    asm("cvt.rna.tf32.f32 %0, %1;" : "=r"(h) : "f"(x));
    return h;
}

// D(16x8) += A(16x8,tf32,row) * B(8x8,tf32,col), fp32 accum.
__device__ __forceinline__ void mma8(float* d, const u32* a, const u32* b) {
    asm volatile(
        "mma.sync.aligned.m16n8k8.row.col.f32.tf32.tf32.f32 "
        "{%0,%1,%2,%3}, {%4,%5,%6,%7}, {%8,%9}, {%0,%1,%2,%3};"
        : "+f"(d[0]), "+f"(d[1]), "+f"(d[2]), "+f"(d[3])
        : "r"(a[0]), "r"(a[1]), "r"(a[2]), "r"(a[3]), "r"(b[0]), "r"(b[1]));
}

__global__ __launch_bounds__(NT) void cin_mma(
    const float* __restrict__ x,    // [4096, 32, 32]
    const float* __restrict__ w0,   // [1024, 128]
    const float* __restrict__ w1,   // [4096, 128]
    float* __restrict__ out)        // [4096, 256]
{
    extern __shared__ __align__(16) float sm[];
    float* const Ud = sm + UD_OFF;   // [4 batch][d*36 + h]
    float* const C0 = sm + C0_OFF;   // [4 batch][d*132 + m]
    float* const Wt = sm + WT_OFF;   // [2 buf][k*136 + n]  (tf32-rounded)

    const int t    = threadIdx.x;
    const int lane = t & 31;
    const int wid  = t >> 5;
    const int wm   = wid >> 2;     // M half: batches 2wm, 2wm+1
    const int wn   = wid & 3;      // N block: n in [32wn, 32wn+32)
    const int lq   = lane >> 2;    // groupID 0..7
    const int lr   = lane & 3;     // threadID_in_group 0..3

    // ---- load inputs transposed into Ud[bs][d][h] ----
    for (int i = t; i < 4096; i += NT) {
        const int bs = i >> 10, h = (i >> 5) & 31, d = i & 31;
        Ud[bs * UD_SZ + d * USTR + h] = x[(size_t)blockIdx.x * 4096 + i];
    }

    float acc[4][4][4];   // [mtile][ntile][creg]
    #pragma unroll
    for (int a = 0; a < 4; ++a)
        #pragma unroll
        for (int b = 0; b < 4; ++b)
            #pragma unroll
            for (int r = 0; r < 4; ++r) acc[a][b][r] = 0.f;

    // ---- prefetch W chunk 0 (tf32-rounded, in regs) ----
    float4 wreg[4];
    {
        const float4* src = reinterpret_cast<const float4*>(w0);
        #pragma unroll
        for (int g = 0; g < 4; ++g) {
            float4 v = src[t * 4 + g];
            v.x = __uint_as_float(cvt_tf32(v.x));
            v.y = __uint_as_float(cvt_tf32(v.y));
            v.z = __uint_as_float(cvt_tf32(v.z));
            v.w = __uint_as_float(cvt_tf32(v.w));
            wreg[g] = v;
        }
    }

    for (int c = 0; c < NCH; ++c) {
        // ======== layer boundary: epilogue 0 ========
        if (c == L0CH) {
            #pragma unroll
            for (int bt = 0; bt < 2; ++bt) {
                const int bs = wm * 2 + bt;
                const size_t bg = (size_t)blockIdx.x * 4 + bs;
                float* const Cb = C0 + bs * C0_SZ;
                #pragma unroll
                for (int nt = 0; nt < 4; ++nt) {
                    const int n = wn * 32 + nt * 8 + 2 * lr;
                    float s0 = 0.f, s1 = 0.f;
                    #pragma unroll
                    for (int sub = 0; sub < 2; ++sub) {
                        const int tt = bt * 2 + sub;
                        const float v0 = fmaxf(acc[tt][nt][0], 0.f);
                        const float v1 = fmaxf(acc[tt][nt][1], 0.f);
                        const float v2 = fmaxf(acc[tt][nt][2], 0.f);
                        const float v3 = fmaxf(acc[tt][nt][3], 0.f);
                        s0 += v0 + v2;
                        s1 += v1 + v3;
                        const int d = sub * 16 + lq;
                        Cb[d * CSTR + n]           = v0;
                        Cb[d * CSTR + n + 1]       = v1;
                        Cb[(d + 8) * CSTR + n]     = v2;
                        Cb[(d + 8) * CSTR + n + 1] = v3;
                    }
                    #pragma unroll
                    for (int o = 4; o < 32; o <<= 1) {
                        s0 += __shfl_xor_sync(0xffffffffu, s0, o);
                        s1 += __shfl_xor_sync(0xffffffffu, s1, o);
                    }
                    if (lq == 0) {
                        out[bg * 256 + n]     = s0;
                        out[bg * 256 + n + 1] = s1;
                    }
                }
            }
            #pragma unroll
            for (int a = 0; a < 4; ++a)
                #pragma unroll
                for (int b = 0; b < 4; ++b)
                    #pragma unroll
                    for (int r = 0; r < 4; ++r) acc[a][b][r] = 0.f;
        }

        // ---- stage prefetched W chunk into buffer c&1 ----
        float* const wb = Wt + (c & 1) * WT_SZ;
        {
            float* dst = wb + (t >> 3) * WSTR + (t & 7) * 16;
            #pragma unroll
            for (int g = 0; g < 4; ++g)
                reinterpret_cast<float4*>(dst)[g] = wreg[g];
        }
        __syncthreads();   // (also publishes Ud on c=0, C0 on c=32)

        // ---- prefetch next chunk ----
        if (c + 1 < NCH) {
            const float* wsrc = (c + 1 < L0CH)
                ? (w0 + (size_t)(c + 1) * 4096)
                : (w1 + (size_t)(c + 1 - L0CH) * 4096);
            const float4* src = reinterpret_cast<const float4*>(wsrc);
            #pragma unroll
            for (int g = 0; g < 4; ++g) {
                float4 v = src[t * 4 + g];
                v.x = __uint_as_float(cvt_tf32(v.x));
                v.y = __uint_as_float(cvt_tf32(v.y));
                v.z = __uint_as_float(cvt_tf32(v.z));
                v.w = __uint_as_float(cvt_tf32(v.w));
                wreg[g] = v;
            }
        }

        // ---- per-chunk operand setup ----
        int h, mb, PS, PSZ;
        const float* Pb;
        if (c < L0CH) { h = c; mb = 0; PS = USTR; PSZ = UD_SZ; Pb = Ud; }
        else {
            const int cl = c - L0CH;
            h = cl >> 2; mb = (cl & 3) * 32; PS = CSTR; PSZ = C0_SZ; Pb = C0;
        }
        const float* pp[4][2];
        float um[4][2];
        #pragma unroll
        for (int tt = 0; tt < 4; ++tt) {
            const int bs = wm * 2 + (tt >> 1);
            const float* Pbatch = Pb + bs * PSZ;
            const float* Ub = Ud + bs * UD_SZ;
            #pragma unroll
            for (int jb = 0; jb < 2; ++jb) {
                const int d = (tt & 1) * 16 + lq + 8 * jb;
                pp[tt][jb] = Pbatch + d * PS + mb + lr;
                um[tt][jb] = Ub[d * USTR + h];
            }
        }
        const float* wp = wb + lr * WSTR + wn * 32 + lq;

        // ---- 4 k8 steps: build A frags in regs, 32 mma ----
        #pragma unroll
        for (int s = 0; s < 4; ++s) {
            u32 bf[4][2];
            #pragma unroll
            for (int nt = 0; nt < 4; ++nt) {
                bf[nt][0] = __float_as_uint(wp[(s * 8) * WSTR + nt * 8]);
                bf[nt][1] = __float_as_uint(wp[(s * 8 + 4) * WSTR + nt * 8]);
            }
            #pragma unroll
            for (int tt = 0; tt < 4; ++tt) {
                u32 ah[4], al[4];
                #pragma unroll
                for (int jk = 0; jk < 2; ++jk)
                    #pragma unroll
                    for (int jb = 0; jb < 2; ++jb) {
                        const float pv = pp[tt][jb][s * 8 + 4 * jk];
                        const float z  = um[tt][jb] * pv;
                        const u32 zh   = cvt_tf32(z);
                        const int idx  = jk * 2 + jb;   // a0..a3 layout
                        ah[idx] = zh;
                        al[idx] = __float_as_uint(z - __uint_as_float(zh));
                    }
                #pragma unroll
                for (int nt = 0; nt < 4; ++nt) {
                    mma8(acc[tt][nt], ah, bf[nt]);
                    mma8(acc[tt][nt], al, bf[nt]);
                }
            }
        }
    }

    // ======== epilogue 1 ========
    #pragma unroll
    for (int bt = 0; bt < 2; ++bt) {
        const int bs = wm * 2 + bt;
        const size_t bg = (size_t)blockIdx.x * 4 + bs;
        #pragma unroll
        for (int nt = 0; nt < 4; ++nt) {
            const int n = wn * 32 + nt * 8 + 2 * lr;
            float s0 = 0.f, s1 = 0.f;
            #pragma unroll
            for (int sub = 0; sub < 2; ++sub) {
                const int tt = bt * 2 + sub;
                s0 += fmaxf(acc[tt][nt][0], 0.f) + fmaxf(acc[tt][nt][2], 0.f);
                s1 += fmaxf(acc[tt][nt][1], 0.f) + fmaxf(acc[tt][nt][3], 0.f);
            }
            #pragma unroll
            for (int o = 4; o < 32; o <<= 1) {
                s0 += __shfl_xor_sync(0xffffffffu, s0, o);
                s1 += __shfl_xor_sync(0xffffffffu, s1, o);
            }
            if (lq == 0) {
                out[bg * 256 + 128 + n]     = s0;
                out[bg * 256 + 128 + n + 1] = s1;
            }
        }
    }
}

extern "C" void kernel_launch(void* const* d_in, const int* in_sizes, int n_in,
                              void* d_out, int out_size) {
    const float* x  = (const float*)d_in[0];   // inputs   [4096,32,32]
    const float* w0 = (const float*)d_in[1];   // filter_0 [1,1024,128]
    const float* w1 = (const float*)d_in[2];   // filter_1 [1,4096,128]
    float* out = (float*)d_out;                // [4096, 256]
    (void)in_sizes; (void)n_in; (void)out_size;

    cudaFuncSetAttribute(cin_mma, cudaFuncAttributeMaxDynamicSharedMemorySize,
                         SMEM_F * sizeof(float));
    cin_mma<<<1024, NT, SMEM_F * sizeof(float)>>>(x, w0, w1, out);
}

// round 7
// speedup vs baseline: 4.1655x; 1.0384x over previous
#include <cuda_runtime.h>

// CIN (xDeepFM) fused 2-layer kernel, round 7 — mma.sync tf32, 2 CTAs/SM.
// B=4096, F=32, D=32, layers [128,128].
//
// GEMM view per batch: 32 d-rows x 128 n, K0=1024, K1=4096.
//   z0[d][k=h*32+m]  = u[h][d]*u[m][d]
//   z1[d][k=h*128+m] = u[h][d]*relu(cur0)[m][d]
// Precision: z split by mantissa mask (zh = z&0xffffe000, zl = z-zh);
// W rounded rna.tf32 once at prefetch. acc += zh*W + zl*W (fp32 accum).
//
// CTA = 2 batches (M64 x N128), 256 threads, 8 warps of M32 x N32
// (warp = one batch x one n-block). 2 CTAs/SM. A fragments built in
// registers; W chunks (KC=32) reg-prefetched, double-buffered smem,
// one __syncthreads per chunk. MMA order: 8x hi then 8x lo (RAW distance 8).

typedef unsigned int u32;

namespace {
constexpr int NT    = 256;
constexpr int L0CH  = 32;     // layer-0 chunks (K=1024/32)
constexpr int NCH   = 160;    // + layer-1 chunks (K=4096/32)
constexpr int USTR  = 36;     // Ud  [d][h] stride (bank-injective)
constexpr int CSTR  = 132;    // C0  [d][m] stride (bank-injective)
constexpr int WSTR  = 136;    // Wt  [k][n] stride (bank-injective)
constexpr int UD_SZ = 32 * USTR;   // 1152 floats / batch
constexpr int C0_SZ = 32 * CSTR;   // 4224 floats / batch
constexpr int WT_SZ = 32 * WSTR;   // 4352 floats / buffer
constexpr int UD_OFF = 0;
constexpr int C0_OFF = UD_OFF + 2 * UD_SZ;   // 2304
constexpr int WT_OFF = C0_OFF + 2 * C0_SZ;   // 10752
constexpr int SMEM_F = WT_OFF + 2 * WT_SZ;   // 19456 floats = 76 KB
}

__device__ __forceinline__ u32 cvt_tf32(float x) {
    u32 h;
    asm("cvt.rna.tf32.f32 %0, %1;" : "=r"(h) : "f"(x));
    return h;
}

// D(16x8) += A(16x8,tf32,row) * B(8x8,tf32,col), fp32 accum.
__device__ __forceinline__ void mma8(float* d, const u32* a, const u32* b) {
    asm volatile(
        "mma.sync.aligned.m16n8k8.row.col.f32.tf32.tf32.f32 "
        "{%0,%1,%2,%3}, {%4,%5,%6,%7}, {%8,%9}, {%0,%1,%2,%3};"
        : "+f"(d[0]), "+f"(d[1]), "+f"(d[2]), "+f"(d[3])
        : "r"(a[0]), "r"(a[1]), "r"(a[2]), "r"(a[3]), "r"(b[0]), "r"(b[1]));
}

__global__ __launch_bounds__(NT, 2) void cin_mma(
    const float* __restrict__ x,    // [4096, 32, 32]
    const float* __restrict__ w0,   // [1024, 128]
    const float* __restrict__ w1,   // [4096, 128]
    float* __restrict__ out)        // [4096, 256]
{
    extern __shared__ __align__(16) float sm[];
    float* const Ud = sm + UD_OFF;   // [2 batch][d*36 + h]
    float* const C0 = sm + C0_OFF;   // [2 batch][d*132 + m]
    float* const Wt = sm + WT_OFF;   // [2 buf][k*136 + n]  (tf32-rounded)

    const int t    = threadIdx.x;
    const int lane = t & 31;
    const int wid  = t >> 5;
    const int bs   = wid >> 2;     // batch within CTA
    const int wn   = wid & 3;      // N block: n in [32wn, 32wn+32)
    const int lq   = lane >> 2;    // groupID 0..7
    const int lr   = lane & 3;     // threadID_in_group 0..3

    // ---- load 2 batches of inputs transposed into Ud[bs][d][h] ----
    for (int i = t; i < 2048; i += NT) {
        const int ib = i >> 10, h = (i >> 5) & 31, d = i & 31;
        Ud[ib * UD_SZ + d * USTR + h] = x[(size_t)blockIdx.x * 2048 + i];
    }

    float acc[2][4][4];   // [mtile(d-half)][ntile][creg]
    #pragma unroll
    for (int a = 0; a < 2; ++a)
        #pragma unroll
        for (int b = 0; b < 4; ++b)
            #pragma unroll
            for (int r = 0; r < 4; ++r) acc[a][b][r] = 0.f;

    // ---- prefetch W chunk 0 (tf32-rounded, in regs) ----
    float4 wreg[4];
    {
        const float4* src = reinterpret_cast<const float4*>(w0);
        #pragma unroll
        for (int g = 0; g < 4; ++g) {
            float4 v = src[t * 4 + g];
            v.x = __uint_as_float(cvt_tf32(v.x));
            v.y = __uint_as_float(cvt_tf32(v.y));
            v.z = __uint_as_float(cvt_tf32(v.z));
            v.w = __uint_as_float(cvt_tf32(v.w));
            wreg[g] = v;
        }
    }

    for (int c = 0; c < NCH; ++c) {
        // ======== layer boundary: epilogue 0 ========
        if (c == L0CH) {
            const size_t bg = (size_t)blockIdx.x * 2 + bs;
            float* const Cb = C0 + bs * C0_SZ;
            #pragma unroll
            for (int nt = 0; nt < 4; ++nt) {
                const int n = wn * 32 + nt * 8 + 2 * lr;
                float s0 = 0.f, s1 = 0.f;
                #pragma unroll
                for (int tt = 0; tt < 2; ++tt) {
                    const float v0 = fmaxf(acc[tt][nt][0], 0.f);
                    const float v1 = fmaxf(acc[tt][nt][1], 0.f);
                    const float v2 = fmaxf(acc[tt][nt][2], 0.f);
                    const float v3 = fmaxf(acc[tt][nt][3], 0.f);
                    s0 += v0 + v2;
                    s1 += v1 + v3;
                    const int d = tt * 16 + lq;
                    Cb[d * CSTR + n]           = v0;
                    Cb[d * CSTR + n + 1]       = v1;
                    Cb[(d + 8) * CSTR + n]     = v2;
                    Cb[(d + 8) * CSTR + n + 1] = v3;
                }
                #pragma unroll
                for (int o = 4; o < 32; o <<= 1) {
                    s0 += __shfl_xor_sync(0xffffffffu, s0, o);
                    s1 += __shfl_xor_sync(0xffffffffu, s1, o);
                }
                if (lq == 0) {
                    out[bg * 256 + n]     = s0;
                    out[bg * 256 + n + 1] = s1;
                }
            }
            #pragma unroll
            for (int a = 0; a < 2; ++a)
                #pragma unroll
                for (int b = 0; b < 4; ++b)
                    #pragma unroll
                    for (int r = 0; r < 4; ++r) acc[a][b][r] = 0.f;
        }

        // ---- stage prefetched W chunk into buffer c&1 ----
        float* const wb = Wt + (c & 1) * WT_SZ;
        {
            float* dst = wb + (t >> 3) * WSTR + (t & 7) * 16;
            #pragma unroll
            for (int g = 0; g < 4; ++g)
                reinterpret_cast<float4*>(dst)[g] = wreg[g];
        }
        __syncthreads();   // publishes Wt (and Ud on c=0, C0 on c=32)

        // ---- prefetch next chunk (in compute shadow) ----
        if (c + 1 < NCH) {
            const float* wsrc = (c + 1 < L0CH)
                ? (w0 + (size_t)(c + 1) * 4096)
                : (w1 + (size_t)(c + 1 - L0CH) * 4096);
            const float4* src = reinterpret_cast<const float4*>(wsrc);
            #pragma unroll
            for (int g = 0; g < 4; ++g) {
                float4 v = src[t * 4 + g];
                v.x = __uint_as_float(cvt_tf32(v.x));
                v.y = __uint_as_float(cvt_tf32(v.y));
                v.z = __uint_as_float(cvt_tf32(v.z));
                v.w = __uint_as_float(cvt_tf32(v.w));
                wreg[g] = v;
            }
        }

        // ---- per-chunk operand setup ----
        int h, mb, PS, PSZ;
        const float* Pb;
        if (c < L0CH) { h = c; mb = 0; PS = USTR; PSZ = UD_SZ; Pb = Ud; }
        else {
            const int cl = c - L0CH;
            h = cl >> 2; mb = (cl & 3) * 32; PS = CSTR; PSZ = C0_SZ; Pb = C0;
        }
        const float* pp[2][2];
        float um[2][2];
        {
            const float* Pbatch = Pb + bs * PSZ;
            const float* Ub = Ud + bs * UD_SZ;
            #pragma unroll
            for (int tt = 0; tt < 2; ++tt)
                #pragma unroll
                for (int jb = 0; jb < 2; ++jb) {
                    const int d = tt * 16 + lq + 8 * jb;
                    pp[tt][jb] = Pbatch + d * PS + mb + lr;
                    um[tt][jb] = Ub[d * USTR + h];
                }
        }
        const float* wp = wb + lr * WSTR + wn * 32 + lq;

        // ---- 4 k8 steps: build A frags, then 8 hi-mma + 8 lo-mma ----
        #pragma unroll
        for (int s = 0; s < 4; ++s) {
            u32 bf[4][2];
            #pragma unroll
            for (int nt = 0; nt < 4; ++nt) {
                bf[nt][0] = __float_as_uint(wp[(s * 8) * WSTR + nt * 8]);
                bf[nt][1] = __float_as_uint(wp[(s * 8 + 4) * WSTR + nt * 8]);
            }
            u32 ah[2][4], al[2][4];
            #pragma unroll
            for (int tt = 0; tt < 2; ++tt)
                #pragma unroll
                for (int jk = 0; jk < 2; ++jk)
                    #pragma unroll
                    for (int jb = 0; jb < 2; ++jb) {
                        const float pv = pp[tt][jb][s * 8 + 4 * jk];
                        const float z  = um[tt][jb] * pv;
                        const u32 zh   = __float_as_uint(z) & 0xffffe000u;
                        const int idx  = jk * 2 + jb;
                        ah[tt][idx] = zh;
                        al[tt][idx] =
                            __float_as_uint(z - __uint_as_float(zh));
                    }
            #pragma unroll
            for (int nt = 0; nt < 4; ++nt)
                #pragma unroll
                for (int tt = 0; tt < 2; ++tt)
                    mma8(acc[tt][nt], ah[tt], bf[nt]);
            #pragma unroll
            for (int nt = 0; nt < 4; ++nt)
                #pragma unroll
                for (int tt = 0; tt < 2; ++tt)
                    mma8(acc[tt][nt], al[tt], bf[nt]);
        }
    }

    // ======== epilogue 1 ========
    {
        const size_t bg = (size_t)blockIdx.x * 2 + bs;
        #pragma unroll
        for (int nt = 0; nt < 4; ++nt) {
            const int n = wn * 32 + nt * 8 + 2 * lr;
            float s0 = 0.f, s1 = 0.f;
            #pragma unroll
            for (int tt = 0; tt < 2; ++tt) {
                s0 += fmaxf(acc[tt][nt][0], 0.f) + fmaxf(acc[tt][nt][2], 0.f);
                s1 += fmaxf(acc[tt][nt][1], 0.f) + fmaxf(acc[tt][nt][3], 0.f);
            }
            #pragma unroll
            for (int o = 4; o < 32; o <<= 1) {
                s0 += __shfl_xor_sync(0xffffffffu, s0, o);
                s1 += __shfl_xor_sync(0xffffffffu, s1, o);
            }
            if (lq == 0) {
                out[bg * 256 + 128 + n]     = s0;
                out[bg * 256 + 128 + n + 1] = s1;
            }
        }
    }
}

extern "C" void kernel_launch(void* const* d_in, const int* in_sizes, int n_in,
                              void* d_out, int out_size) {
    const float* x  = (const float*)d_in[0];   // inputs   [4096,32,32]
    const float* w0 = (const float*)d_in[1];   // filter_0 [1,1024,128]
    const float* w1 = (const float*)d_in[2];   // filter_1 [1,4096,128]
    float* out = (float*)d_out;                // [4096, 256]
    (void)in_sizes; (void)n_in; (void)out_size;

    cudaFuncSetAttribute(cin_mma, cudaFuncAttributeMaxDynamicSharedMemorySize,
                         SMEM_F * sizeof(float));
    cin_mma<<<2048, NT, SMEM_F * sizeof(float)>>>(x, w0, w1, out);
}